// round 16
// baseline (speedup 1.0000x reference)
#include <cuda_runtime.h>
#include <cuda_fp16.h>
#include <cstdint>
#include <math.h>

// Problem dims
#define DS 1024
#define DN 64
#define DH 1024
#define DI 1024
#define DM (DS * DN)

#define NKT 64           // global k-tiles (16 k each)
#define NMT 4096         // global m-tiles (16 m each)
#define NNT 128          // global n-tiles (8 i each)
#define NCHUNK 16        // k-chunks of 64

// GEMM tile: CTA 128m x 128i, 4 warps (wm 0..1, wn 0..1), warp 64x64
// Chunk = 64 k (4 k-steps). Stage: A 16KB + B 16KB = 32KB (8192 words);
// 3 stages + 128-float sacc; 2 CTAs/SM.
#define STAGE_W 8192
#define SMEM_BYTES ((3 * STAGE_W + 128) * 4)

// Scratch
__device__ uint4 g_ah[NKT * NMT * 32];   // 128 MB: A fragments fp16
__device__ uint2 g_bh[NKT * NNT * 32];   // 2 MB: B fragments fp16
__device__ float g_u[DI * DN];           // u transposed [i][n]
__device__ float g_apart[8 * DM];        // per-i-eighth partial scores
__device__ float g_cpart[4 * DN * DH];   // per-s-quarter partial context
__device__ float g_alpha_fallback[DM];

__device__ __forceinline__ uint32_t smem_u32(const void* p) {
    uint32_t a;
    asm("{ .reg .u64 t; cvta.to.shared.u64 t, %1; cvt.u32.u64 %0, t; }" : "=r"(a) : "l"(p));
    return a;
}
__device__ __forceinline__ void cp16(uint32_t saddr, const void* g) {
    asm volatile("cp.async.cg.shared.global [%0], [%1], 16;" :: "r"(saddr), "l"(g));
}
__device__ __forceinline__ float tanh_apx(float x) {
    float y;
    asm("tanh.approx.f32 %0, %1;" : "=f"(y) : "f"(x));
    return y;
}
__device__ __forceinline__ uint32_t f2h2(float lo, float hi) {
    uint32_t r;
    asm("cvt.rn.f16x2.f32 %0, %1, %2;" : "=r"(r) : "f"(hi), "f"(lo));
    return r;
}
__device__ __forceinline__ void mma_f16(float* d, const uint32_t* a, const uint32_t* b) {
    asm volatile(
        "mma.sync.aligned.m16n8k16.row.col.f32.f16.f16.f32 "
        "{%0,%1,%2,%3}, {%4,%5,%6,%7}, {%8,%9}, {%0,%1,%2,%3};"
        : "+f"(d[0]), "+f"(d[1]), "+f"(d[2]), "+f"(d[3])
        : "r"(a[0]), "r"(a[1]), "r"(a[2]), "r"(a[3]), "r"(b[0]), "r"(b[1]));
}

// ---------------------------------------------------------------------------
// Convert A (out_e fp32 [65536,1024]) -> canonical m16n8k16 A-fragment fp16.
// ---------------------------------------------------------------------------
__global__ void k_convA(const float* __restrict__ A) {
    __shared__ uint32_t sA[16][516];
    const int mt = blockIdx.x;
    const int tid = threadIdx.x;
    const int lane = tid & 31, wid = tid >> 5;
    const float* src = A + (size_t)mt * 16 * DH;

    for (int idx = tid; idx < 4096; idx += 256) {
        const int row = idx >> 8;
        const int col4 = idx & 255;
        const float4 v = *reinterpret_cast<const float4*>(src + row * DH + col4 * 4);
        sA[row][col4 * 2]     = f2h2(v.x, v.y);
        sA[row][col4 * 2 + 1] = f2h2(v.z, v.w);
    }
    __syncthreads();

    const int r = lane >> 2, c = lane & 3;
#pragma unroll
    for (int t8 = 0; t8 < 8; t8++) {
        const int kt = wid * 8 + t8;
        const int kw = kt * 8 + c;
        uint4 o;
        o.x = sA[r][kw];
        o.y = sA[r + 8][kw];
        o.z = sA[r][kw + 4];
        o.w = sA[r + 8][kw + 4];
        g_ah[((size_t)kt * NMT + mt) * 32 + lane] = o;
    }
}

// ---------------------------------------------------------------------------
// Convert B (W2 fp32 [1024,1024]) -> canonical B-fragment fp16.
// ---------------------------------------------------------------------------
__global__ void k_convB(const float* __restrict__ W2) {
    __shared__ uint32_t sB[8][516];
    const int nb = blockIdx.x;
    const int tid = threadIdx.x;
    const int lane = tid & 31, wid = tid >> 5;
    const float* src = W2 + (size_t)nb * 8 * DH;

    for (int idx = tid; idx < 2048; idx += 256) {
        const int row = idx >> 8;
        const int col4 = idx & 255;
        const float4 v = *reinterpret_cast<const float4*>(src + row * DH + col4 * 4);
        sB[row][col4 * 2]     = f2h2(v.x, v.y);
        sB[row][col4 * 2 + 1] = f2h2(v.z, v.w);
    }
    __syncthreads();

    const int np = lane >> 2, c = lane & 3;
#pragma unroll
    for (int t8 = 0; t8 < 8; t8++) {
        const int kt = wid * 8 + t8;
        const int kw = kt * 8 + c;
        uint2 o;
        o.x = sB[np][kw];
        o.y = sB[np][kw + 4];
        g_bh[((size_t)kt * NNT + nb) * 32 + lane] = o;
    }
}

// ---------------------------------------------------------------------------
// Kernel: u_t[i][n] = b1[i] + b2[i] + dot(hidden_d[n,:], W1[i,:])
// ---------------------------------------------------------------------------
__global__ void k_u(const float* __restrict__ hd, const float* __restrict__ W1,
                    const float* __restrict__ b1, const float* __restrict__ b2) {
    __shared__ float sw[8 * 1056];
    const int i0 = blockIdx.x * 8;
    const int t = threadIdx.x;

    for (int off = t * 4; off < 8 * 1024; off += 256 * 4) {
        const int row = off >> 10;
        const int col = off & 1023;
        *reinterpret_cast<float4*>(&sw[row * 1056 + col]) =
            *reinterpret_cast<const float4*>(W1 + (size_t)(i0 + row) * DH + col);
    }
    __syncthreads();

    const int il = t & 7;
    const int n0 = (t >> 3) * 2;
    const float* wrow = &sw[il * 1056];
    const float* h0 = hd + (size_t)n0 * DH;
    const float* h1 = hd + (size_t)(n0 + 1) * DH;

    float a0 = 0.f, a1 = 0.f;
#pragma unroll 4
    for (int h4 = 0; h4 < 256; h4++) {
        const float4 w = *reinterpret_cast<const float4*>(wrow + h4 * 4);
        const float4 x0 = *reinterpret_cast<const float4*>(h0 + h4 * 4);
        const float4 x1 = *reinterpret_cast<const float4*>(h1 + h4 * 4);
        a0 = fmaf(w.x, x0.x, fmaf(w.y, x0.y, fmaf(w.z, x0.z, fmaf(w.w, x0.w, a0))));
        a1 = fmaf(w.x, x1.x, fmaf(w.y, x1.y, fmaf(w.z, x1.z, fmaf(w.w, x1.w, a1))));
    }
    const int i = i0 + il;
    const float bb = b1[i] + b2[i];
    g_u[i * DN + n0] = a0 + bb;
    g_u[i * DN + n0 + 1] = a1 + bb;
}

// ---------------------------------------------------------------------------
// GEMM: prepacked fp16 fragments, 64-k chunks (16 barriers), cp.async
// 3-stage ring, 128 threads, CTA 128m x 128i, 2 CTAs/SM.
// Epilogue: u slice staged into freed stage smem (stride 68, conflict-free).
// grid (8 i-eighths, 512 m-blocks).
// ---------------------------------------------------------------------------
__global__ __launch_bounds__(128, 2) void k_gemm(const float* __restrict__ W3) {
    extern __shared__ uint32_t smu[];
    float* sacc = reinterpret_cast<float*>(smu + 3 * STAGE_W);
    float* us = reinterpret_cast<float*>(smu);
    const uint32_t sb = smem_u32(smu);

    const int tid = threadIdx.x;
    const int lane = tid & 31;
    const int wid = tid >> 5;
    const int wm = wid >> 1, wn = wid & 1;
    const int i0 = blockIdx.x * 128;
    const int m0 = blockIdx.y * 128;

    const uint4* aS = g_ah + (size_t)(m0 >> 4) * 32;  // + kt*131072 uint4
    const uint2* bS = g_bh + (size_t)(i0 >> 3) * 32;  // + kt*4096 uint2

    // Per chunk: A = 1024 x 16B (4 ks * 8 mt * 32 lanes),
    //            B = 1024 x 16B (4 ks * 16 nt * 16 lane-pairs). 16/thread.
#define ISSUE(ck)                                                              \
    do {                                                                       \
        const uint32_t dstb = sb + ((ck) % 3) * 32768;                         \
        const size_t ko = (size_t)(4 * (ck));                                  \
        _Pragma("unroll")                                                      \
        for (int j = 0; j < 16; j++) {                                         \
            const int u = j * 128 + tid;                                       \
            if (u < 1024) {                                                    \
                const int ks = u >> 8, rest = u & 255;                         \
                cp16(dstb + u * 16,                                            \
                     (const void*)(aS + (ko + ks) * (size_t)131072 + rest));   \
            } else {                                                           \
                const int v = u - 1024;                                        \
                const int ks = v >> 8, rest = v & 255;                         \
                cp16(dstb + 16384 + v * 16,                                    \
                     (const void*)(bS + (ko + ks) * (size_t)4096 + rest * 2)); \
            }                                                                  \
        }                                                                      \
        asm volatile("cp.async.commit_group;");                                \
    } while (0)

    float acc[4][8][4];
#pragma unroll
    for (int mt = 0; mt < 4; mt++)
#pragma unroll
        for (int nt = 0; nt < 8; nt++)
#pragma unroll
            for (int e = 0; e < 4; e++) acc[mt][nt][e] = 0.f;

    ISSUE(0);
    ISSUE(1);
    sacc[tid] = 0.f;

    for (int ck = 0; ck < NCHUNK; ck++) {
        asm volatile("cp.async.wait_group 1;" ::: "memory");
        __syncthreads();
        if (ck + 2 < NCHUNK) ISSUE(ck + 2);
        else asm volatile("cp.async.commit_group;");

        const uint32_t* st = smu + (ck % 3) * STAGE_W;
#pragma unroll
        for (int ks = 0; ks < 4; ks++) {
            uint32_t afr[4][4];
#pragma unroll
            for (int mt = 0; mt < 4; mt++) {
                const uint4 v = *reinterpret_cast<const uint4*>(
                    st + ((ks * 8 + wm * 4 + mt) * 32 + lane) * 4);
                afr[mt][0] = v.x; afr[mt][1] = v.y; afr[mt][2] = v.z; afr[mt][3] = v.w;
            }
            uint32_t bfr[8][2];
#pragma unroll
            for (int nt = 0; nt < 8; nt++) {
                const uint2 v = *reinterpret_cast<const uint2*>(
                    st + 4096 + ks * 1024 + ((wn * 8 + nt) * 32 + lane) * 2);
                bfr[nt][0] = v.x; bfr[nt][1] = v.y;
            }
#pragma unroll
            for (int mt = 0; mt < 4; mt++)
#pragma unroll
                for (int nt = 0; nt < 8; nt++)
                    mma_f16(acc[mt][nt], afr[mt], bfr[nt]);
        }
    }

    // Stage u slice [i0, i0+128) x [0,64) into freed stage smem, stride 68
    // (bank = (4*i + n) mod 32 -> conflict-free epilogue reads).
    __syncthreads();   // all warps out of the mainloop before overwriting stages
#pragma unroll
    for (int q = 0; q < 16; q++) {
        const int idx4 = q * 128 + tid;
        const int il = idx4 >> 4;
        const int n4 = (idx4 & 15) * 4;
        const float4 v = *reinterpret_cast<const float4*>(
            g_u + (size_t)(i0 + il) * DN + n4);
        us[il * 68 + n4 + 0] = v.x;
        us[il * 68 + n4 + 1] = v.y;
        us[il * 68 + n4 + 2] = v.z;
        us[il * 68 + n4 + 3] = v.w;
    }
    __syncthreads();

    // Epilogue: z = acc + u[i][n]; partial[m] += W3[i]*tanh(z)
    const int rbase = wm * 64 + (lane >> 2);
    const int ibl_base = wn * 64 + (lane & 3) * 2;
#pragma unroll
    for (int mt = 0; mt < 4; mt++) {
#pragma unroll
        for (int h = 0; h < 2; h++) {
            const int row = rbase + mt * 16 + 8 * h;
            const int n = (m0 + row) & (DN - 1);
            float s = 0.f;
#pragma unroll
            for (int nt = 0; nt < 8; nt++) {
                const int ibl = ibl_base + nt * 8;
                const float z0 = acc[mt][nt][h * 2 + 0] + us[ibl * 68 + n];
                const float z1 = acc[mt][nt][h * 2 + 1] + us[(ibl + 1) * 68 + n];
                s = fmaf(__ldg(&W3[i0 + ibl]), tanh_apx(z0), s);
                s = fmaf(__ldg(&W3[i0 + ibl + 1]), tanh_apx(z1), s);
            }
            s += __shfl_xor_sync(0xffffffffu, s, 1);
            s += __shfl_xor_sync(0xffffffffu, s, 2);
            if ((lane & 3) == 0) atomicAdd(&sacc[row], s);
        }
    }
    __syncthreads();
    g_apart[blockIdx.x * DM + m0 + tid] = sacc[tid];
}

// ---------------------------------------------------------------------------
// Softmax over S per column n (sums 8 i-eighth partials + b3).
// ---------------------------------------------------------------------------
__global__ void k_softmax(float* __restrict__ alpha, const float* __restrict__ b3) {
    const int n = blockIdx.x;
    const int t = threadIdx.x;
    __shared__ float sred[16];
    const float b3v = b3[0];

    float loc[4];
    float mx = -1e30f;
#pragma unroll
    for (int qq = 0; qq < 4; qq++) {
        const int idx = (t + qq * 256) * DN + n;
        float v = b3v;
#pragma unroll
        for (int p = 0; p < 8; p++) v += g_apart[p * DM + idx];
        loc[qq] = v;
        mx = fmaxf(mx, v);
    }
#pragma unroll
    for (int off = 16; off; off >>= 1) mx = fmaxf(mx, __shfl_xor_sync(0xffffffffu, mx, off));
    if ((t & 31) == 0) sred[t >> 5] = mx;
    __syncthreads();
    if (t == 0) {
        float v = sred[0];
        for (int ww = 1; ww < 8; ww++) v = fmaxf(v, sred[ww]);
        sred[0] = v;
    }
    __syncthreads();
    mx = sred[0];

    float sum = 0.f;
#pragma unroll
    for (int qq = 0; qq < 4; qq++) {
        loc[qq] = expf(loc[qq] - mx);
        sum += loc[qq];
    }
#pragma unroll
    for (int off = 16; off; off >>= 1) sum += __shfl_xor_sync(0xffffffffu, sum, off);
    if ((t & 31) == 0) sred[8 + (t >> 5)] = sum;
    __syncthreads();
    if (t == 0) {
        float v = 0.f;
        for (int ww = 0; ww < 8; ww++) v += sred[8 + ww];
        sred[8] = v;
    }
    __syncthreads();
    const float inv = 1.0f / sred[8];
#pragma unroll
    for (int qq = 0; qq < 4; qq++) alpha[(t + qq * 256) * DN + n] = loc[qq] * inv;
}

// ---------------------------------------------------------------------------
// Context from fp16 A-FRAGMENTS (reads 128MB instead of 256MB fp32).
// grid (64, 4, 4), 256 threads; warp w handles s_l = it*8 + w.
// ---------------------------------------------------------------------------
__global__ void k_ctx_frag(const float* __restrict__ alpha) {
    const int kt = blockIdx.x;     // h-tile (16 h's)
    const int mtg = blockIdx.y;    // n-group (16 n's)
    const int sc = blockIdx.z;     // s-quarter (256 s's)
    const int tid = threadIdx.x;
    const int lane = tid & 31, w = tid >> 5;
    const int r = lane >> 2;

    __shared__ float sal[256 * 16];   // alpha slice [s_local][n_local]
    __shared__ float red[8][258];

    for (int idx = tid; idx < 4096; idx += 256) {
        const int s_l = idx >> 4, n_l = idx & 15;
        sal[idx] = alpha[(sc * 256 + s_l) * DN + mtg * 16 + n_l];
    }
    __syncthreads();

    const uint4* p = g_ah +
        ((size_t)kt * NMT + (size_t)sc * 1024 + mtg) * 32 + lane;

    float acc[8];
#pragma unroll
    for (int q = 0; q < 8; q++) acc[q] = 0.f;

#pragma unroll 4
    for (int it = 0; it < 32; it++) {
        const int s_l = it * 8 + w;
        const uint4 v = p[(size_t)s_l * 128];
        const float a1 = sal[s_l * 16 + r];
        const float a2 = sal[s_l * 16 + r + 8];
        float2 f;
        f = __half22float2(*reinterpret_cast<const __half2*>(&v.x));
        acc[0] = fmaf(a1, f.x, acc[0]); acc[1] = fmaf(a1, f.y, acc[1]);
        f = __half22float2(*reinterpret_cast<const __half2*>(&v.z));
        acc[2] = fmaf(a1, f.x, acc[2]); acc[3] = fmaf(a1, f.y, acc[3]);
        f = __half22float2(*reinterpret_cast<const __half2*>(&v.y));
        acc[4] = fmaf(a2, f.x, acc[4]); acc[5] = fmaf(a2, f.y, acc[5]);
        f = __half22float2(*reinterpret_cast<const __half2*>(&v.w));
        acc[6] = fmaf(a2, f.x, acc[6]); acc[7] = fmaf(a2, f.y, acc[7]);
    }

#pragma unroll
    for (int q = 0; q < 8; q++) red[w][lane * 8 + q] = acc[q];
    __syncthreads();

    {
        const int lane_of = tid >> 3, q = tid & 7;
        float s = 0.f;
#pragma unroll
        for (int ww = 0; ww < 8; ww++) s += red[ww][tid];
        const int r_of = lane_of >> 2, c_of = lane_of & 3;
        const int n = mtg * 16 + r_of + ((q & 4) ? 8 : 0);
        const int hh = kt * 16 + 2 * c_of + (q & 1) + ((q & 2) ? 8 : 0);
        g_cpart[(size_t)sc * DN * DH + n * DH + hh] = s;
    }
}

// Sum the 4 s-quarter partials.
__global__ void k_ctx_sum(float* __restrict__ cdst) {
    const int idx = (blockIdx.x * 256 + threadIdx.x) * 4;
    float4 s = {0, 0, 0, 0};
#pragma unroll
    for (int p = 0; p < 4; p++) {
        const float4 v = *reinterpret_cast<const float4*>(&g_cpart[(size_t)p * DN * DH + idx]);
        s.x += v.x; s.y += v.y; s.z += v.z; s.w += v.w;
    }
    *reinterpret_cast<float4*>(cdst + idx) = s;
}

// ---------------------------------------------------------------------------
extern "C" void kernel_launch(void* const* d_in, const int* in_sizes, int n_in,
                              void* d_out, int out_size) {
    const float* out_e    = (const float*)d_in[0];
    const float* hidden_d = (const float*)d_in[1];
    const float* W1       = (const float*)d_in[2];
    const float* b1       = (const float*)d_in[3];
    const float* W2       = (const float*)d_in[4];
    const float* b2       = (const float*)d_in[5];
    const float* W3       = (const float*)d_in[6];
    const float* b3       = (const float*)d_in[7];
    float* out = (float*)d_out;

    float* cdst = out;
    float* alpha;
    if (out_size >= DN * DH + DM) {
        alpha = out + DN * DH;
    } else {
        void* p = nullptr;
        cudaGetSymbolAddress(&p, g_alpha_fallback);
        alpha = (float*)p;
    }

    cudaFuncSetAttribute(k_gemm, cudaFuncAttributeMaxDynamicSharedMemorySize,
                         SMEM_BYTES);

    k_convA<<<NMT, 256>>>(out_e);
    k_convB<<<NNT, 256>>>(W2);
    k_u<<<DI / 8, 256>>>(hidden_d, W1, b1, b2);
    k_gemm<<<dim3(8, 512), 128, SMEM_BYTES>>>(W3);
    k_softmax<<<DN, 256>>>(alpha, b3);
    k_ctx_frag<<<dim3(64, 4, 4), 256>>>(alpha);
    k_ctx_sum<<<DN * DH / 1024, 256>>>(cdst);
}

// round 17
// speedup vs baseline: 1.0137x; 1.0137x over previous
#include <cuda_runtime.h>
#include <cuda_fp16.h>
#include <cstdint>
#include <math.h>

// Problem dims
#define DS 1024
#define DN 64
#define DH 1024
#define DI 1024
#define DM (DS * DN)

#define NKT 64           // global k-tiles (16 k each)
#define NMT 4096         // global m-tiles (16 m each)
#define NNT 128          // global n-tiles (8 i each)
#define NCHUNK 16        // k-chunks of 64

// GEMM tile: CTA 128m x 128i, 4 warps (wm 0..1, wn 0..1), warp 64x64
// Chunk = 64 k (4 k-steps). Stage: A 16KB + B 16KB = 32KB (8192 words);
// 3 stages + 128-float sacc; 2 CTAs/SM.
#define STAGE_W 8192
#define SMEM_BYTES ((3 * STAGE_W + 128) * 4)

// Scratch
__device__ uint4 g_ah[NKT * NMT * 32];   // 128 MB: A fragments fp16
__device__ uint2 g_bh[NKT * NNT * 32];   // 2 MB: B fragments fp16
__device__ float g_u[DI * DN];           // u transposed [i][n]
__device__ float g_apart[8 * DM];        // per-i-eighth partial scores
__device__ float g_alpha_fallback[DM];

__device__ __forceinline__ uint32_t smem_u32(const void* p) {
    uint32_t a;
    asm("{ .reg .u64 t; cvta.to.shared.u64 t, %1; cvt.u32.u64 %0, t; }" : "=r"(a) : "l"(p));
    return a;
}
__device__ __forceinline__ void cp16(uint32_t saddr, const void* g) {
    asm volatile("cp.async.cg.shared.global [%0], [%1], 16;" :: "r"(saddr), "l"(g));
}
__device__ __forceinline__ float tanh_apx(float x) {
    float y;
    asm("tanh.approx.f32 %0, %1;" : "=f"(y) : "f"(x));
    return y;
}
__device__ __forceinline__ uint32_t f2h2(float lo, float hi) {
    uint32_t r;
    asm("cvt.rn.f16x2.f32 %0, %1, %2;" : "=r"(r) : "f"(hi), "f"(lo));
    return r;
}
__device__ __forceinline__ void mma_f16(float* d, const uint32_t* a, const uint32_t* b) {
    asm volatile(
        "mma.sync.aligned.m16n8k16.row.col.f32.f16.f16.f32 "
        "{%0,%1,%2,%3}, {%4,%5,%6,%7}, {%8,%9}, {%0,%1,%2,%3};"
        : "+f"(d[0]), "+f"(d[1]), "+f"(d[2]), "+f"(d[3])
        : "r"(a[0]), "r"(a[1]), "r"(a[2]), "r"(a[3]), "r"(b[0]), "r"(b[1]));
}

// ---------------------------------------------------------------------------
// Convert A (out_e fp32 [65536,1024]) -> canonical m16n8k16 A-fragment fp16.
// ---------------------------------------------------------------------------
__global__ void k_convA(const float* __restrict__ A) {
    __shared__ uint32_t sA[16][516];
    const int mt = blockIdx.x;
    const int tid = threadIdx.x;
    const int lane = tid & 31, wid = tid >> 5;
    const float* src = A + (size_t)mt * 16 * DH;

    for (int idx = tid; idx < 4096; idx += 256) {
        const int row = idx >> 8;
        const int col4 = idx & 255;
        const float4 v = *reinterpret_cast<const float4*>(src + row * DH + col4 * 4);
        sA[row][col4 * 2]     = f2h2(v.x, v.y);
        sA[row][col4 * 2 + 1] = f2h2(v.z, v.w);
    }
    __syncthreads();

    const int r = lane >> 2, c = lane & 3;
#pragma unroll
    for (int t8 = 0; t8 < 8; t8++) {
        const int kt = wid * 8 + t8;
        const int kw = kt * 8 + c;
        uint4 o;
        o.x = sA[r][kw];
        o.y = sA[r + 8][kw];
        o.z = sA[r][kw + 4];
        o.w = sA[r + 8][kw + 4];
        g_ah[((size_t)kt * NMT + mt) * 32 + lane] = o;
    }
}

// ---------------------------------------------------------------------------
// Convert B (W2 fp32 [1024,1024]) -> canonical B-fragment fp16.
// ---------------------------------------------------------------------------
__global__ void k_convB(const float* __restrict__ W2) {
    __shared__ uint32_t sB[8][516];
    const int nb = blockIdx.x;
    const int tid = threadIdx.x;
    const int lane = tid & 31, wid = tid >> 5;
    const float* src = W2 + (size_t)nb * 8 * DH;

    for (int idx = tid; idx < 2048; idx += 256) {
        const int row = idx >> 8;
        const int col4 = idx & 255;
        const float4 v = *reinterpret_cast<const float4*>(src + row * DH + col4 * 4);
        sB[row][col4 * 2]     = f2h2(v.x, v.y);
        sB[row][col4 * 2 + 1] = f2h2(v.z, v.w);
    }
    __syncthreads();

    const int np = lane >> 2, c = lane & 3;
#pragma unroll
    for (int t8 = 0; t8 < 8; t8++) {
        const int kt = wid * 8 + t8;
        const int kw = kt * 8 + c;
        uint2 o;
        o.x = sB[np][kw];
        o.y = sB[np][kw + 4];
        g_bh[((size_t)kt * NNT + nb) * 32 + lane] = o;
    }
}

// ---------------------------------------------------------------------------
// Kernel: u_t[i][n] = b1[i] + b2[i] + dot(hidden_d[n,:], W1[i,:])
// ---------------------------------------------------------------------------
__global__ void k_u(const float* __restrict__ hd, const float* __restrict__ W1,
                    const float* __restrict__ b1, const float* __restrict__ b2) {
    __shared__ float sw[8 * 1056];
    const int i0 = blockIdx.x * 8;
    const int t = threadIdx.x;

    for (int off = t * 4; off < 8 * 1024; off += 256 * 4) {
        const int row = off >> 10;
        const int col = off & 1023;
        *reinterpret_cast<float4*>(&sw[row * 1056 + col]) =
            *reinterpret_cast<const float4*>(W1 + (size_t)(i0 + row) * DH + col);
    }
    __syncthreads();

    const int il = t & 7;
    const int n0 = (t >> 3) * 2;
    const float* wrow = &sw[il * 1056];
    const float* h0 = hd + (size_t)n0 * DH;
    const float* h1 = hd + (size_t)(n0 + 1) * DH;

    float a0 = 0.f, a1 = 0.f;
#pragma unroll 4
    for (int h4 = 0; h4 < 256; h4++) {
        const float4 w = *reinterpret_cast<const float4*>(wrow + h4 * 4);
        const float4 x0 = *reinterpret_cast<const float4*>(h0 + h4 * 4);
        const float4 x1 = *reinterpret_cast<const float4*>(h1 + h4 * 4);
        a0 = fmaf(w.x, x0.x, fmaf(w.y, x0.y, fmaf(w.z, x0.z, fmaf(w.w, x0.w, a0))));
        a1 = fmaf(w.x, x1.x, fmaf(w.y, x1.y, fmaf(w.z, x1.z, fmaf(w.w, x1.w, a1))));
    }
    const int i = i0 + il;
    const float bb = b1[i] + b2[i];
    g_u[i * DN + n0] = a0 + bb;
    g_u[i * DN + n0 + 1] = a1 + bb;
}

// ---------------------------------------------------------------------------
// GEMM: prepacked fp16 fragments, 64-k chunks (16 barriers), cp.async
// 3-stage ring, 128 threads, CTA 128m x 128i, 2 CTAs/SM.
// Epilogue: u slice staged into freed stage smem (stride 68, conflict-free).
// grid (8 i-eighths, 512 m-blocks).
// ---------------------------------------------------------------------------
__global__ __launch_bounds__(128, 2) void k_gemm(const float* __restrict__ W3) {
    extern __shared__ uint32_t smu[];
    float* sacc = reinterpret_cast<float*>(smu + 3 * STAGE_W);
    float* us = reinterpret_cast<float*>(smu);
    const uint32_t sb = smem_u32(smu);

    const int tid = threadIdx.x;
    const int lane = tid & 31;
    const int wid = tid >> 5;
    const int wm = wid >> 1, wn = wid & 1;
    const int i0 = blockIdx.x * 128;
    const int m0 = blockIdx.y * 128;

    const uint4* aS = g_ah + (size_t)(m0 >> 4) * 32;  // + kt*131072 uint4
    const uint2* bS = g_bh + (size_t)(i0 >> 3) * 32;  // + kt*4096 uint2

#define ISSUE(ck)                                                              \
    do {                                                                       \
        const uint32_t dstb = sb + ((ck) % 3) * 32768;                         \
        const size_t ko = (size_t)(4 * (ck));                                  \
        _Pragma("unroll")                                                      \
        for (int j = 0; j < 16; j++) {                                         \
            const int u = j * 128 + tid;                                       \
            if (u < 1024) {                                                    \
                const int ks = u >> 8, rest = u & 255;                         \
                cp16(dstb + u * 16,                                            \
                     (const void*)(aS + (ko + ks) * (size_t)131072 + rest));   \
            } else {                                                           \
                const int v = u - 1024;                                        \
                const int ks = v >> 8, rest = v & 255;                         \
                cp16(dstb + 16384 + v * 16,                                    \
                     (const void*)(bS + (ko + ks) * (size_t)4096 + rest * 2)); \
            }                                                                  \
        }                                                                      \
        asm volatile("cp.async.commit_group;");                                \
    } while (0)

    float acc[4][8][4];
#pragma unroll
    for (int mt = 0; mt < 4; mt++)
#pragma unroll
        for (int nt = 0; nt < 8; nt++)
#pragma unroll
            for (int e = 0; e < 4; e++) acc[mt][nt][e] = 0.f;

    ISSUE(0);
    ISSUE(1);
    sacc[tid] = 0.f;

    for (int ck = 0; ck < NCHUNK; ck++) {
        asm volatile("cp.async.wait_group 1;" ::: "memory");
        __syncthreads();
        if (ck + 2 < NCHUNK) ISSUE(ck + 2);
        else asm volatile("cp.async.commit_group;");

        const uint32_t* st = smu + (ck % 3) * STAGE_W;
#pragma unroll
        for (int ks = 0; ks < 4; ks++) {
            uint32_t afr[4][4];
#pragma unroll
            for (int mt = 0; mt < 4; mt++) {
                const uint4 v = *reinterpret_cast<const uint4*>(
                    st + ((ks * 8 + wm * 4 + mt) * 32 + lane) * 4);
                afr[mt][0] = v.x; afr[mt][1] = v.y; afr[mt][2] = v.z; afr[mt][3] = v.w;
            }
            uint32_t bfr[8][2];
#pragma unroll
            for (int nt = 0; nt < 8; nt++) {
                const uint2 v = *reinterpret_cast<const uint2*>(
                    st + 4096 + ks * 1024 + ((wn * 8 + nt) * 32 + lane) * 2);
                bfr[nt][0] = v.x; bfr[nt][1] = v.y;
            }
#pragma unroll
            for (int mt = 0; mt < 4; mt++)
#pragma unroll
                for (int nt = 0; nt < 8; nt++)
                    mma_f16(acc[mt][nt], afr[mt], bfr[nt]);
        }
    }

    // Stage u slice [i0, i0+128) x [0,64) into freed stage smem, stride 68
    // (bank = (4*i + n) mod 32 -> conflict-free epilogue reads).
    __syncthreads();
#pragma unroll
    for (int q = 0; q < 16; q++) {
        const int idx4 = q * 128 + tid;
        const int il = idx4 >> 4;
        const int n4 = (idx4 & 15) * 4;
        const float4 v = *reinterpret_cast<const float4*>(
            g_u + (size_t)(i0 + il) * DN + n4);
        us[il * 68 + n4 + 0] = v.x;
        us[il * 68 + n4 + 1] = v.y;
        us[il * 68 + n4 + 2] = v.z;
        us[il * 68 + n4 + 3] = v.w;
    }
    __syncthreads();

    // Epilogue: z = acc + u[i][n]; partial[m] += W3[i]*tanh(z)
    const int rbase = wm * 64 + (lane >> 2);
    const int ibl_base = wn * 64 + (lane & 3) * 2;
#pragma unroll
    for (int mt = 0; mt < 4; mt++) {
#pragma unroll
        for (int h = 0; h < 2; h++) {
            const int row = rbase + mt * 16 + 8 * h;
            const int n = (m0 + row) & (DN - 1);
            float s = 0.f;
#pragma unroll
            for (int nt = 0; nt < 8; nt++) {
                const int ibl = ibl_base + nt * 8;
                const float z0 = acc[mt][nt][h * 2 + 0] + us[ibl * 68 + n];
                const float z1 = acc[mt][nt][h * 2 + 1] + us[(ibl + 1) * 68 + n];
                s = fmaf(__ldg(&W3[i0 + ibl]), tanh_apx(z0), s);
                s = fmaf(__ldg(&W3[i0 + ibl + 1]), tanh_apx(z1), s);
            }
            s += __shfl_xor_sync(0xffffffffu, s, 1);
            s += __shfl_xor_sync(0xffffffffu, s, 2);
            if ((lane & 3) == 0) atomicAdd(&sacc[row], s);
        }
    }
    __syncthreads();
    g_apart[blockIdx.x * DM + m0 + tid] = sacc[tid];
}

// ---------------------------------------------------------------------------
// Softmax over S per column n (sums 8 i-eighth partials + b3).
// Also zeroes the context output region (poisoned by the harness) so that
// k_ctx_frag can accumulate into it with atomics.
// ---------------------------------------------------------------------------
__global__ void k_softmax(float* __restrict__ alpha, const float* __restrict__ b3,
                          float* __restrict__ cdst) {
    const int n = blockIdx.x;
    const int t = threadIdx.x;
    __shared__ float sred[16];
    const float b3v = b3[0];

    // zero c output: 65536 floats over 64*256 threads = one float4 each
    {
        const int gi = (n * 256 + t) * 4;
        *reinterpret_cast<float4*>(cdst + gi) = make_float4(0.f, 0.f, 0.f, 0.f);
    }

    float loc[4];
    float mx = -1e30f;
#pragma unroll
    for (int qq = 0; qq < 4; qq++) {
        const int idx = (t + qq * 256) * DN + n;
        float v = b3v;
#pragma unroll
        for (int p = 0; p < 8; p++) v += g_apart[p * DM + idx];
        loc[qq] = v;
        mx = fmaxf(mx, v);
    }
#pragma unroll
    for (int off = 16; off; off >>= 1) mx = fmaxf(mx, __shfl_xor_sync(0xffffffffu, mx, off));
    if ((t & 31) == 0) sred[t >> 5] = mx;
    __syncthreads();
    if (t == 0) {
        float v = sred[0];
        for (int ww = 1; ww < 8; ww++) v = fmaxf(v, sred[ww]);
        sred[0] = v;
    }
    __syncthreads();
    mx = sred[0];

    float sum = 0.f;
#pragma unroll
    for (int qq = 0; qq < 4; qq++) {
        loc[qq] = expf(loc[qq] - mx);
        sum += loc[qq];
    }
#pragma unroll
    for (int off = 16; off; off >>= 1) sum += __shfl_xor_sync(0xffffffffu, sum, off);
    if ((t & 31) == 0) sred[8 + (t >> 5)] = sum;
    __syncthreads();
    if (t == 0) {
        float v = 0.f;
        for (int ww = 0; ww < 8; ww++) v += sred[8 + ww];
        sred[8] = v;
    }
    __syncthreads();
    const float inv = 1.0f / sred[8];
#pragma unroll
    for (int qq = 0; qq < 4; qq++) alpha[(t + qq * 256) * DN + n] = loc[qq] * inv;
}

// ---------------------------------------------------------------------------
// Context from fp16 A-FRAGMENTS; accumulates s-quarter results directly
// into cdst via atomicAdd (REDG) — no partial buffer, no sum kernel.
// grid (64, 4, 4), 256 threads; warp w handles s_l = it*8 + w.
// ---------------------------------------------------------------------------
__global__ void k_ctx_frag(const float* __restrict__ alpha,
                           float* __restrict__ cdst) {
    const int kt = blockIdx.x;     // h-tile (16 h's)
    const int mtg = blockIdx.y;    // n-group (16 n's)
    const int sc = blockIdx.z;     // s-quarter (256 s's)
    const int tid = threadIdx.x;
    const int lane = tid & 31, w = tid >> 5;
    const int r = lane >> 2;

    __shared__ float sal[256 * 16];   // alpha slice [s_local][n_local]
    __shared__ float red[8][258];

    for (int idx = tid; idx < 4096; idx += 256) {
        const int s_l = idx >> 4, n_l = idx & 15;
        sal[idx] = alpha[(sc * 256 + s_l) * DN + mtg * 16 + n_l];
    }
    __syncthreads();

    const uint4* p = g_ah +
        ((size_t)kt * NMT + (size_t)sc * 1024 + mtg) * 32 + lane;

    float acc[8];
#pragma unroll
    for (int q = 0; q < 8; q++) acc[q] = 0.f;

#pragma unroll 4
    for (int it = 0; it < 32; it++) {
        const int s_l = it * 8 + w;
        const uint4 v = p[(size_t)s_l * 128];
        const float a1 = sal[s_l * 16 + r];
        const float a2 = sal[s_l * 16 + r + 8];
        float2 f;
        f = __half22float2(*reinterpret_cast<const __half2*>(&v.x));
        acc[0] = fmaf(a1, f.x, acc[0]); acc[1] = fmaf(a1, f.y, acc[1]);
        f = __half22float2(*reinterpret_cast<const __half2*>(&v.z));
        acc[2] = fmaf(a1, f.x, acc[2]); acc[3] = fmaf(a1, f.y, acc[3]);
        f = __half22float2(*reinterpret_cast<const __half2*>(&v.y));
        acc[4] = fmaf(a2, f.x, acc[4]); acc[5] = fmaf(a2, f.y, acc[5]);
        f = __half22float2(*reinterpret_cast<const __half2*>(&v.w));
        acc[6] = fmaf(a2, f.x, acc[6]); acc[7] = fmaf(a2, f.y, acc[7]);
    }

#pragma unroll
    for (int q = 0; q < 8; q++) red[w][lane * 8 + q] = acc[q];
    __syncthreads();

    {
        const int lane_of = tid >> 3, q = tid & 7;
        float s = 0.f;
#pragma unroll
        for (int ww = 0; ww < 8; ww++) s += red[ww][tid];
        const int r_of = lane_of >> 2, c_of = lane_of & 3;
        const int n = mtg * 16 + r_of + ((q & 4) ? 8 : 0);
        const int hh = kt * 16 + 2 * c_of + (q & 1) + ((q & 2) ? 8 : 0);
        atomicAdd(&cdst[n * DH + hh], s);
    }
}

// ---------------------------------------------------------------------------
extern "C" void kernel_launch(void* const* d_in, const int* in_sizes, int n_in,
                              void* d_out, int out_size) {
    const float* out_e    = (const float*)d_in[0];
    const float* hidden_d = (const float*)d_in[1];
    const float* W1       = (const float*)d_in[2];
    const float* b1       = (const float*)d_in[3];
    const float* W2       = (const float*)d_in[4];
    const float* b2       = (const float*)d_in[5];
    const float* W3       = (const float*)d_in[6];
    const float* b3       = (const float*)d_in[7];
    float* out = (float*)d_out;

    float* cdst = out;
    float* alpha;
    if (out_size >= DN * DH + DM) {
        alpha = out + DN * DH;
    } else {
        void* p = nullptr;
        cudaGetSymbolAddress(&p, g_alpha_fallback);
        alpha = (float*)p;
    }

    cudaFuncSetAttribute(k_gemm, cudaFuncAttributeMaxDynamicSharedMemorySize,
                         SMEM_BYTES);

    k_convA<<<NMT, 256>>>(out_e);
    k_convB<<<NNT, 256>>>(W2);
    k_u<<<DI / 8, 256>>>(hidden_d, W1, b1, b2);
    k_gemm<<<dim3(8, 512), 128, SMEM_BYTES>>>(W3);
    k_softmax<<<DN, 256>>>(alpha, b3, cdst);
    k_ctx_frag<<<dim3(64, 4, 4), 256>>>(alpha, cdst);
}